// round 3
// baseline (speedup 1.0000x reference)
#include <cuda_runtime.h>
#include <cuda_fp16.h>
#include <mma.h>
#include <cuda_pipeline.h>
#include <cstdint>

using namespace nvcuda;

// ---------------- problem constants ----------------
#define B_SZ        8
#define L_SZ        1048576
#define KWIN        500
#define T_WIN       2097            // (L-K)/K + 1
#define TILES_PER_B 17              // ceil(2097/128)
#define GRID_MAIN   (B_SZ * TILES_PER_B)   // 136
#define NCHUNK      125             // 500 positions / 4 per chunk (K-chunk = 32)
#define OP_SCALE    128.0f          // operands pre-scaled by 2^7 (keeps lo-parts normal fp16)
#define OUT_DESCALE (1.0f / 16384.0f)  // 2^-14

// smem byte offsets (dynamic smem, 16B-aligned)
#define OFF_EMBH  0                 // 257*8 halfs = 4112 B
#define OFF_EMBL  4112
#define OFF_AH0   8224              // each A buf: 128 rows * 80 B = 10240
#define OFF_AL0   (OFF_AH0 + 10240)
#define OFF_AH1   (OFF_AL0 + 10240)
#define OFF_AL1   (OFF_AH1 + 10240)
#define OFF_BH0   (OFF_AL1 + 10240) // each B buf: 256 rows * 80 B = 20480
#define OFF_BL0   (OFF_BH0 + 20480)
#define OFF_BH1   (OFF_BL0 + 20480)
#define OFF_BL1   (OFF_BH1 + 20480) // ends 131104
#define OFF_GAT   OFF_AH0           // epilogue scratch: 128*260*4 = 133120 (reuses bufs)
#define SMEM_ALLOC (OFF_AH0 + 128 * 260 * 4)   // 141344

// ---------------- persistent device scratch ----------------
__device__ __align__(16) __half g_wh_hi[256 * 4000];  // fused w1||w2 * 128, hi fp16, [o][kg], kg=kp*8+e
__device__ __align__(16) __half g_wh_lo[256 * 4000];  // residual lo fp16
__device__ __align__(16) __half g_emb_hi[257 * 8];
__device__ __align__(16) __half g_emb_lo[257 * 8];
__device__ float g_pooled[B_SZ * 128];

// ---------------- prep: split-precision conversion + pooled zero ----------------
__global__ void malconv_prep_kernel(const float* __restrict__ w1, const float* __restrict__ w2,
                                    const float* __restrict__ emb)
{
    const int bid = blockIdx.x, tid = threadIdx.x;
    if (bid < 1000) {
        const int idx = bid * 1024 + tid;          // 1,024,000 = 256*4000
        const int o  = idx / 4000;
        const int r  = idx % 4000;
        const int kp = r >> 3, e = r & 7;          // kg = kp*8 + e
        const float* w = (o < 128) ? w1 : w2;
        const int oc = o & 127;
        const float v = w[oc * 4000 + e * 500 + kp] * OP_SCALE;
        const __half h = __float2half_rn(v);
        g_wh_hi[idx] = h;
        g_wh_lo[idx] = __float2half_rn(v - __half2float(h));
    } else {
        for (int i = tid; i < 257 * 8; i += 1024) {
            const float v = emb[i] * OP_SCALE;
            const __half h = __float2half_rn(v);
            g_emb_hi[i] = h;
            g_emb_lo[i] = __float2half_rn(v - __half2float(h));
        }
        if (tid < B_SZ * 128) g_pooled[tid] = 0.0f;
    }
}

// ---------------- main fused conv GEMM + gate + maxpool ----------------
__global__ void __launch_bounds__(256, 1)
malconv_main_kernel(const int* __restrict__ x,
                    const float* __restrict__ b1, const float* __restrict__ b2)
{
    extern __shared__ __align__(16) char sb[];
    const int tid = threadIdx.x;

    const int bidx = blockIdx.x / TILES_PER_B;     // batch
    const int tt   = blockIdx.x % TILES_PER_B;     // M-tile
    const int t0   = tt * 128;

    // embedding tables -> smem
    __half* embh = (__half*)(sb + OFF_EMBH);
    __half* embl = (__half*)(sb + OFF_EMBL);
    for (int i = tid; i < 257 * 8; i += 256) { embh[i] = g_emb_hi[i]; embl[i] = g_emb_lo[i]; }

    // ---- A-fill role: 2 threads per window row; each covers 2 conv positions ----
    const int arow = tid >> 1, ah_ = tid & 1;
    int trow = t0 + arow; if (trow >= T_WIN) trow = T_WIN - 1;   // clamp, masked later
    const int* xrow = x + (size_t)bidx * L_SZ + (size_t)trow * KWIN + 2 * ah_;

    // ---- prologue: async-copy B chunk 0 (hi+lo) ----
    {
#pragma unroll
        for (int i = 0; i < 8; i++) {
            const int idx = tid + (i & 3) * 256;   // 0..1023 -> 256 rows x 4 quads
            const int o = idx >> 2, q = idx & 3;
            if (i < 4)
                __pipeline_memcpy_async(sb + OFF_BH0 + o * 80 + q * 16, g_wh_hi + (size_t)o * 4000 + q * 8, 16);
            else
                __pipeline_memcpy_async(sb + OFF_BL0 + o * 80 + q * 16, g_wh_lo + (size_t)o * 4000 + q * 8, 16);
        }
        __pipeline_commit();
    }
    int2 xv = *(const int2*)xrow;                  // x prefetch, chunk 0
    __syncthreads();                               // emb tables ready

    // ---- warp tiling: 8 warps = 2 (M) x 4 (N); warp tile 64x64 ----
    const int wid = tid >> 5;
    const int wm = wid & 1;        // M block of 64
    const int wn = wid >> 1;       // N block of 64

    wmma::fragment<wmma::accumulator, 16, 16, 16, float> acc[4][4];
#pragma unroll
    for (int i = 0; i < 4; i++)
#pragma unroll
        for (int j = 0; j < 4; j++)
            wmma::fill_fragment(acc[i][j], 0.0f);

    for (int c = 0; c < NCHUNK; ++c) {
        const int s = c & 1;
        char* AHbuf = sb + (s ? OFF_AH1 : OFF_AH0);
        char* ALbuf = sb + (s ? OFF_AL1 : OFF_AL0);
        char* BHbuf = sb + (s ? OFF_BH1 : OFF_BH0);
        char* BLbuf = sb + (s ? OFF_BL1 : OFF_BL0);

        // 1. fill A(c): hi + lo, 2 positions per thread
        {
            const int2 xcur = xv;
            if (c + 1 < NCHUNK) xv = *(const int2*)(xrow + (c + 1) * 4);
#pragma unroll
            for (int i = 0; i < 2; i++) {
                const int v = i ? xcur.y : xcur.x;
                const int pl = 2 * ah_ + i;
                *(uint4*)(AHbuf + arow * 80 + pl * 16) = ((const uint4*)embh)[v];
                *(uint4*)(ALbuf + arow * 80 + pl * 16) = ((const uint4*)embl)[v];
            }
        }

        // 2. wait for B(c), 3. barrier
        __pipeline_wait_prior(0);
        __syncthreads();

        // 4. issue B(c+1) into the other buffers
        if (c + 1 < NCHUNK) {
            char* BHn = sb + (s ? OFF_BH0 : OFF_BH1);
            char* BLn = sb + (s ? OFF_BL0 : OFF_BL1);
            const size_t kof = (size_t)(c + 1) * 32;
#pragma unroll
            for (int i = 0; i < 8; i++) {
                const int idx = tid + (i & 3) * 256;
                const int o = idx >> 2, q = idx & 3;
                if (i < 4)
                    __pipeline_memcpy_async(BHn + o * 80 + q * 16, g_wh_hi + (size_t)o * 4000 + kof + q * 8, 16);
                else
                    __pipeline_memcpy_async(BLn + o * 80 + q * 16, g_wh_lo + (size_t)o * 4000 + kof + q * 8, 16);
            }
            __pipeline_commit();
        }

        // 5. compensated MMA on chunk c: acc += Ah*Bh + Ah*Bl + Al*Bh
#pragma unroll
        for (int ks = 0; ks < 2; ks++) {
            wmma::fragment<wmma::matrix_a, 16, 16, 16, __half, wmma::row_major> Ah[4], Al[4];
#pragma unroll
            for (int i = 0; i < 4; i++) {
                wmma::load_matrix_sync(Ah[i], (__half*)AHbuf + (wm * 64 + i * 16) * 40 + ks * 16, 40);
                wmma::load_matrix_sync(Al[i], (__half*)ALbuf + (wm * 64 + i * 16) * 40 + ks * 16, 40);
            }
#pragma unroll
            for (int j = 0; j < 4; j++) {
                wmma::fragment<wmma::matrix_b, 16, 16, 16, __half, wmma::col_major> Bh, Bl;
                wmma::load_matrix_sync(Bh, (__half*)BHbuf + (wn * 64 + j * 16) * 40 + ks * 16, 40);
                wmma::load_matrix_sync(Bl, (__half*)BLbuf + (wn * 64 + j * 16) * 40 + ks * 16, 40);
#pragma unroll
                for (int i = 0; i < 4; i++) {
                    wmma::mma_sync(acc[i][j], Ah[i], Bh, acc[i][j]);
                    wmma::mma_sync(acc[i][j], Ah[i], Bl, acc[i][j]);
                    wmma::mma_sync(acc[i][j], Al[i], Bh, acc[i][j]);
                }
            }
        }
    }

    // ---- epilogue: accum -> smem, descale + bias + gate, mask, column max ----
    __syncthreads();
    float* gat = (float*)(sb + OFF_GAT);           // [row][o], stride 260 floats
#pragma unroll
    for (int i = 0; i < 4; i++)
#pragma unroll
        for (int j = 0; j < 4; j++)
            wmma::store_matrix_sync(gat + (wm * 64 + i * 16) * 260 + wn * 64 + j * 16,
                                    acc[i][j], 260, wmma::mem_row_major);
    __syncthreads();

    if (tid < 128) {
        const int o = tid;
        const float b1v = b1[o], b2v = b2[o];
        int nval = T_WIN - t0; if (nval > 128) nval = 128;
        float m = 0.0f;
        for (int r = 0; r < nval; r++) {
            const float c1 = gat[r * 260 + o]       * OUT_DESCALE + b1v;
            const float c2 = gat[r * 260 + o + 128] * OUT_DESCALE + b2v;
            const float g  = fmaxf(c1, 0.0f) * (1.0f / (1.0f + __expf(-c2)));
            m = fmaxf(m, g);
        }
        atomicMax((int*)(g_pooled + bidx * 128 + o), __float_as_int(m));  // m >= 0
    }
}

// ---------------- dense head ----------------
__global__ void malconv_head_kernel(const float* __restrict__ wd1, const float* __restrict__ bd1,
                                    const float* __restrict__ wd2, const float* __restrict__ bd2,
                                    float* __restrict__ out)
{
    __shared__ float psh[B_SZ * 128];
    __shared__ float hsh[B_SZ * 128];
    const int tid = threadIdx.x;                   // 1024 threads
    psh[tid] = g_pooled[tid];
    __syncthreads();
    const int b = tid >> 7, j = tid & 127;
    float acc = bd1[j];
    const float* wr = wd1 + j * 128;
#pragma unroll 8
    for (int o = 0; o < 128; o++) acc += psh[b * 128 + o] * wr[o];
    hsh[tid] = fmaxf(acc, 0.0f);
    __syncthreads();
    if (tid < B_SZ) {
        float a2 = bd2[0];
#pragma unroll 8
        for (int jj = 0; jj < 128; jj++) a2 += hsh[tid * 128 + jj] * wd2[jj];
        out[tid] = 1.0f / (1.0f + __expf(-a2));
    }
}

// ---------------- launch ----------------
extern "C" void kernel_launch(void* const* d_in, const int* in_sizes, int n_in,
                              void* d_out, int out_size) {
    (void)in_sizes; (void)n_in; (void)out_size;
    const int*   x   = (const int*)d_in[0];
    const float* emb = (const float*)d_in[1];
    const float* w1  = (const float*)d_in[2];
    const float* b1  = (const float*)d_in[3];
    const float* w2  = (const float*)d_in[4];
    const float* b2  = (const float*)d_in[5];
    const float* wd1 = (const float*)d_in[6];
    const float* bd1 = (const float*)d_in[7];
    const float* wd2 = (const float*)d_in[8];
    const float* bd2 = (const float*)d_in[9];
    float* out = (float*)d_out;

    cudaFuncSetAttribute(malconv_main_kernel,
                         cudaFuncAttributeMaxDynamicSharedMemorySize, SMEM_ALLOC);

    malconv_prep_kernel<<<1001, 1024>>>(w1, w2, emb);
    malconv_main_kernel<<<GRID_MAIN, 256, SMEM_ALLOC>>>(x, b1, b2);
    malconv_head_kernel<<<1, 1024>>>(wd1, bd1, wd2, bd2, out);
}